// round 14
// baseline (speedup 1.0000x reference)
#include <cuda_runtime.h>
#include <cuda_fp16.h>
#include <math.h>
#include <stdint.h>

#define BATCH 2
#define SEQ 2048
#define DMODEL 2048
#define NHEAD 16
#define HDIM 128
#define MROWS (BATCH * SEQ)          // 4096
#define ATT_SCALE 0.08838834764831845f  // 1/sqrt(128)
#define LOG2E 1.4426950408889634f

// Scratch (device globals: allocation-free per harness rules)
__device__ __half hx_q[(size_t)MROWS * DMODEL];   // fp16 inputs
__device__ __half hx_k[(size_t)MROWS * DMODEL];
__device__ __half hx_v[(size_t)MROWS * DMODEL];
__device__ __half hw_q[(size_t)DMODEL * DMODEL];  // fp16 weights
__device__ __half hw_k[(size_t)DMODEL * DMODEL];
__device__ __half hw_v[(size_t)DMODEL * DMODEL];
__device__ __half hw_o[(size_t)DMODEL * DMODEL];
__device__ __half h_q[(size_t)MROWS * DMODEL];    // projected q (pre-scaled)
__device__ __half h_k[(size_t)MROWS * DMODEL];
__device__ __half h_v[(size_t)MROWS * DMODEL];
__device__ __half h_a[(size_t)MROWS * DMODEL];    // attention output

// ===========================================================================
// helpers
// ===========================================================================
__device__ __forceinline__ uint32_t smem_u32(const void* p) {
    uint32_t a;
    asm("{ .reg .u64 t; cvta.to.shared.u64 t, %1; cvt.u32.u64 %0, t; }"
        : "=r"(a) : "l"(p));
    return a;
}

__device__ __forceinline__ void cp16(uint32_t dst, const void* src) {
    asm volatile("cp.async.cg.shared.global [%0], [%1], 16;"
                 :: "r"(dst), "l"(src));
}

__device__ __forceinline__ void mma_f16(float* d, const uint32_t* a,
                                        const uint32_t* b)
{
    asm volatile(
        "mma.sync.aligned.m16n8k16.row.col.f32.f16.f16.f32 "
        "{%0,%1,%2,%3}, {%4,%5,%6,%7}, {%8,%9}, {%0,%1,%2,%3};"
        : "+f"(d[0]), "+f"(d[1]), "+f"(d[2]), "+f"(d[3])
        : "r"(a[0]), "r"(a[1]), "r"(a[2]), "r"(a[3]),
          "r"(b[0]), "r"(b[1]));
}

__device__ __forceinline__ void ldsm4(uint32_t* r, uint32_t a) {
    asm volatile("ldmatrix.sync.aligned.m8n8.x4.shared.b16 {%0,%1,%2,%3}, [%4];"
                 : "=r"(r[0]), "=r"(r[1]), "=r"(r[2]), "=r"(r[3]) : "r"(a));
}
__device__ __forceinline__ void ldsm4t(uint32_t* r, uint32_t a) {
    asm volatile("ldmatrix.sync.aligned.m8n8.x4.trans.shared.b16 {%0,%1,%2,%3}, [%4];"
                 : "=r"(r[0]), "=r"(r[1]), "=r"(r[2]), "=r"(r[3]) : "r"(a));
}

// exp2 on a packed pair of (fp32 -> fp16) values; result is an MMA A-frag word
__device__ __forceinline__ uint32_t ex2_h2(float x, float y) {
    __half2 hv = __floats2half2_rn(x, y);
    uint32_t u = *(uint32_t*)&hv;
    uint32_t r;
    asm("ex2.approx.f16x2 %0, %1;" : "=r"(r) : "r"(u));
    return r;
}

// ===========================================================================
// single fp32 -> fp16 conversion pass: z = 0..2 activations, 3..6 weights
// ===========================================================================
__device__ __forceinline__ uint2 cvt4(float4 v) {
    union { __half2 h[2]; uint2 u; } p;
    p.h[0] = __floats2half2_rn(v.x, v.y);
    p.h[1] = __floats2half2_rn(v.z, v.w);
    return p.u;
}

#define ACT_BLOCKS ((MROWS * DMODEL / 4) / 1024)   // 2048
#define W_BLOCKS ((DMODEL * DMODEL / 4) / 1024)    // 1024

__global__ void conv_all(const float4* __restrict__ q,
                         const float4* __restrict__ k,
                         const float4* __restrict__ v,
                         const float4* __restrict__ w0,
                         const float4* __restrict__ w1,
                         const float4* __restrict__ w2,
                         const float4* __restrict__ w3,
                         uint2* __restrict__ oq, uint2* __restrict__ ok,
                         uint2* __restrict__ ov,
                         uint2* __restrict__ o0, uint2* __restrict__ o1,
                         uint2* __restrict__ o2, uint2* __restrict__ o3)
{
    const int z = blockIdx.y;
    const float4* src;
    uint2* dst;
    if (z < 3) {
        src = (z == 0) ? q : (z == 1) ? k : v;
        dst = (z == 0) ? oq : (z == 1) ? ok : ov;
    } else {
        if (blockIdx.x >= W_BLOCKS) return;
        src = (z == 3) ? w0 : (z == 4) ? w1 : (z == 5) ? w2 : w3;
        dst = (z == 3) ? o0 : (z == 4) ? o1 : (z == 5) ? o2 : o3;
    }
    const int base = blockIdx.x * 1024 + threadIdx.x;
    float4 v0 = src[base];
    float4 v1 = src[base + 256];
    float4 v2 = src[base + 512];
    float4 v3 = src[base + 768];
    dst[base] = cvt4(v0);
    dst[base + 256] = cvt4(v1);
    dst[base + 512] = cvt4(v2);
    dst[base + 768] = cvt4(v3);
}

// ===========================================================================
// fp16 mma.sync GEMM core v3: CTA 128x128, 128 threads, 4 warps (2x2 of
// 64x64), BK=64, 2-stage cp.async, ONE sync per K-iter, 3 CTAs/SM.
// ===========================================================================
#define TBM 128
#define TBN 128
#define GK 2048
#define GN 2048
#define GBKH 64
#define AP 72
#define ASTGH (TBM * AP)
#define BSTGH (TBN * AP)
#define STGH (ASTGH + BSTGH)
#define GEMM_SMEM (2 * STGH * 2)      // 73728 B -> 3 CTAs/SM
#define NT (GK / GBKH)                // 32
#define GEMM_THREADS 128

__device__ __forceinline__ void gemm_core(
    const __half* __restrict__ A, const __half* __restrict__ W,
    const float* __restrict__ bias, void* __restrict__ Cout,
    float scale, int half_out, int bx, int by)
{
    extern __shared__ __half gsmh[];

    const int tid = threadIdx.x;
    const int lane = tid & 31;
    const int warp = tid >> 5;
    const int wm = warp & 1;
    const int wn = warp >> 1;
    const int m0 = by * TBM;
    const int n0 = bx * TBN;

    const uint32_t sbase = smem_u32(gsmh);
    const int cr = tid >> 3;
    const int cc = tid & 7;

    float acc[4][8][4];
#pragma unroll
    for (int i = 0; i < 4; i++)
#pragma unroll
        for (int j = 0; j < 8; j++)
#pragma unroll
            for (int r = 0; r < 4; r++) acc[i][j][r] = 0.0f;

    auto issue = [&](int t, int buf) {
        const __half* Ab = A + (size_t)m0 * GK + t * GBKH;
        const __half* Wb = W + (size_t)n0 * GK + t * GBKH;
        const uint32_t sa = sbase + (uint32_t)buf * STGH * 2u;
        const uint32_t sb = sa + ASTGH * 2u;
#pragma unroll
        for (int i = 0; i < 8; i++) {
            const int r = cr + i * 16;
            cp16(sa + (uint32_t)(r * AP + cc * 8) * 2u,
                 Ab + (size_t)r * GK + cc * 8);
            cp16(sb + (uint32_t)(r * AP + cc * 8) * 2u,
                 Wb + (size_t)r * GK + cc * 8);
        }
        asm volatile("cp.async.commit_group;");
    };

    issue(0, 0);

    const uint32_t a_lane_off =
        (uint32_t)((wm * 64 + (lane & 15)) * AP + ((lane >> 4) * 8)) * 2u;
    const uint32_t b_lane_off =
        (uint32_t)((wn * 64 + (lane & 7) + ((lane >> 4) & 1) * 8) * AP
                   + (((lane >> 3) & 1) * 8)) * 2u;

    for (int t = 0; t < NT; ++t) {
        asm volatile("cp.async.wait_group 0;");
        __syncthreads();
        // load of t+1 (other buffer) overlaps compute of t; the sync above
        // guarantees all reads of buf^1 from iter t-1 are done (WAR safe).
        if (t + 1 < NT) issue(t + 1, (t + 1) & 1);

        const uint32_t sa = sbase + (uint32_t)(t & 1) * STGH * 2u;
        const uint32_t aaddr = sa + a_lane_off;
        const uint32_t baddr = sa + ASTGH * 2u + b_lane_off;

#pragma unroll
        for (int ks = 0; ks < 4; ++ks) {
            uint32_t bf[4][4];
#pragma unroll
            for (int np = 0; np < 4; np++)
                ldsm4(bf[np], baddr + (uint32_t)(np * 16 * AP + ks * 16) * 2u);
#pragma unroll
            for (int ms = 0; ms < 4; ms++) {
                uint32_t af[4];
                ldsm4(af, aaddr + (uint32_t)(ms * 16 * AP + ks * 16) * 2u);
#pragma unroll
                for (int np = 0; np < 4; np++) {
                    mma_f16(acc[ms][np * 2], af, bf[np]);
                    mma_f16(acc[ms][np * 2 + 1], af, bf[np] + 2);
                }
            }
        }
    }

    float2 bv[8];
#pragma unroll
    for (int ns = 0; ns < 8; ns++) {
        const int col = n0 + wn * 64 + ns * 8 + 2 * (lane & 3);
        bv[ns] = *(const float2*)(bias + col);
    }

    if (half_out) {
        __half* C = (__half*)Cout;
#pragma unroll
        for (int ms = 0; ms < 4; ms++) {
            const int row0 = m0 + wm * 64 + ms * 16 + (lane >> 2);
#pragma unroll
            for (int ns = 0; ns < 8; ns++) {
                const int col = n0 + wn * 64 + ns * 8 + 2 * (lane & 3);
                __half2 v0 = __floats2half2_rn((acc[ms][ns][0] + bv[ns].x) * scale,
                                               (acc[ms][ns][1] + bv[ns].y) * scale);
                __half2 v1 = __floats2half2_rn((acc[ms][ns][2] + bv[ns].x) * scale,
                                               (acc[ms][ns][3] + bv[ns].y) * scale);
                *(__half2*)(C + (size_t)row0 * GN + col) = v0;
                *(__half2*)(C + (size_t)(row0 + 8) * GN + col) = v1;
            }
        }
    } else {
        float* C = (float*)Cout;
#pragma unroll
        for (int ms = 0; ms < 4; ms++) {
            const int row0 = m0 + wm * 64 + ms * 16 + (lane >> 2);
#pragma unroll
            for (int ns = 0; ns < 8; ns++) {
                const int col = n0 + wn * 64 + ns * 8 + 2 * (lane & 3);
                float2 v0 = make_float2(acc[ms][ns][0] + bv[ns].x,
                                        acc[ms][ns][1] + bv[ns].y);
                float2 v1 = make_float2(acc[ms][ns][2] + bv[ns].x,
                                        acc[ms][ns][3] + bv[ns].y);
                *(float2*)(C + (size_t)row0 * GN + col) = v0;
                *(float2*)(C + (size_t)(row0 + 8) * GN + col) = v1;
            }
        }
    }
}

__global__ __launch_bounds__(GEMM_THREADS, 3)
void gemm_qkv(const __half* __restrict__ xq, const __half* __restrict__ xk,
              const __half* __restrict__ xv,
              const __half* __restrict__ wq, const __half* __restrict__ wk,
              const __half* __restrict__ wv,
              const float* __restrict__ bq, const float* __restrict__ bk,
              const float* __restrict__ bv,
              __half* __restrict__ pq, __half* __restrict__ pk,
              __half* __restrict__ pv)
{
    const int z = blockIdx.z;
    const __half* A = (z == 0) ? xq : (z == 1) ? xk : xv;
    const __half* W = (z == 0) ? wq : (z == 1) ? wk : wv;
    const float* bias = (z == 0) ? bq : (z == 1) ? bk : bv;
    __half* C = (z == 0) ? pq : (z == 1) ? pk : pv;
    const float scale = (z == 0) ? (ATT_SCALE * LOG2E) : 1.0f;
    gemm_core(A, W, bias, C, scale, 1, blockIdx.x, blockIdx.y);
}

__global__ __launch_bounds__(GEMM_THREADS, 3)
void gemm_one(const __half* __restrict__ A, const __half* __restrict__ W,
              const float* __restrict__ bias, void* __restrict__ Cout,
              float scale, int half_out)
{
    gemm_core(A, W, bias, Cout, scale, half_out, blockIdx.x, blockIdx.y);
}

// ===========================================================================
// fp16 flash attention v6: 64-q-row CTAs, 2 CTAs/SM, ex2.approx.f16x2 softmax,
// ONE sync per tile (issue-next-after-sync pipeline).
// ===========================================================================
#define FQ 64
#define FK 64
#define FP 136
#define QTILE_H (FQ * FP)
#define KTILE_H (FK * FP)
#define FLASH_SMEM ((QTILE_H + 4 * KTILE_H) * 2)   // 87040 B
#define FLASH_THREADS 128
#define NQT (SEQ / FQ)                 // 32

__global__ __launch_bounds__(FLASH_THREADS, 2)
void flash_tc(const __half* __restrict__ Q, const __half* __restrict__ K,
              const __half* __restrict__ V, __half* __restrict__ O)
{
    extern __shared__ __half fsmh[];

    const int qt = NQT - 1 - blockIdx.x;   // heavy tiles first
    const int h = blockIdx.y;
    const int b = blockIdx.z;
    const int q0 = qt * FQ;
    const size_t headoff = (size_t)b * SEQ * DMODEL + (size_t)h * HDIM;
    const __half* Qb = Q + headoff;
    const __half* Kb = K + headoff;
    const __half* Vb = V + headoff;

    const int tid = threadIdx.x;
    const int lane = tid & 31;
    const int warp = tid >> 5;
    const int g = lane >> 2;
    const int q4 = lane & 3;

    const uint32_t sQ = smem_u32(fsmh);
    const uint32_t sK0 = sQ + QTILE_H * 2u;
    const uint32_t sV0 = sQ + (QTILE_H + 2 * KTILE_H) * 2u;

#pragma unroll
    for (int i = 0; i < 8; ++i) {
        const int slot = tid + i * FLASH_THREADS;
        const int r = slot >> 4, c = slot & 15;
        cp16(sQ + (uint32_t)(r * FP + c * 8) * 2u,
             Qb + (size_t)(q0 + r) * DMODEL + c * 8);
    }

    auto issue_kv = [&](int kt) {
        const int buf = kt & 1;
        const int k0 = kt * FK;
        const uint32_t dK = sK0 + (uint32_t)buf * KTILE_H * 2u;
        const uint32_t dV = sV0 + (uint32_t)buf * KTILE_H * 2u;
#pragma unroll
        for (int i = 0; i < 8; ++i) {
            const int slot = tid + i * FLASH_THREADS;
            const int r = slot >> 4, c = slot & 15;
            cp16(dK + (uint32_t)(r * FP + c * 8) * 2u,
                 Kb + (size_t)(k0 + r) * DMODEL + c * 8);
            cp16(dV + (uint32_t)(r * FP + c * 8) * 2u,
                 Vb + (size_t)(k0 + r) * DMODEL + c * 8);
        }
        asm volatile("cp.async.commit_group;");
    };

    issue_kv(0);   // group 0 = Q + KV0

    float m0 = -INFINITY, m1 = -INFINITY, l0 = 0.0f, l1 = 0.0f;
    float acco[16][4];
#pragma unroll
    for (int j = 0; j < 16; j++)
#pragma unroll
        for (int r = 0; r < 4; r++) acco[j][r] = 0.0f;

    const int ar = warp * 16 + g;

    const uint32_t qa_off =
        (uint32_t)((warp * 16 + (lane & 15)) * FP + ((lane >> 4) * 8)) * 2u;
    const uint32_t kb4_off =
        (uint32_t)(((lane & 7) + ((lane >> 4) & 1) * 8) * FP
                   + (((lane >> 3) & 1) * 8)) * 2u;
    const uint32_t vt4_off =
        (uint32_t)(((lane & 7) + ((lane >> 3) & 1) * 8) * FP
                   + ((lane >> 4) * 8)) * 2u;

    uint32_t qf[8][4];
    bool qloaded = false;

    for (int kt = 0; kt <= qt; ++kt) {
        const int buf = kt & 1;
        const uint32_t sKc = sK0 + (uint32_t)buf * KTILE_H * 2u;
        const uint32_t sVc = sV0 + (uint32_t)buf * KTILE_H * 2u;

        asm volatile("cp.async.wait_group 0;");
        __syncthreads();
        // next tile loads into the other buffer; sync above makes the WAR
        // (iter kt-1's reads of that buffer) safe. Load overlaps compute.
        if (kt + 1 <= qt) issue_kv(kt + 1);

        if (!qloaded) {
#pragma unroll
            for (int ks = 0; ks < 8; ++ks)
                ldsm4(qf[ks], sQ + qa_off + (uint32_t)(ks * 16) * 2u);
            qloaded = true;
        }

        // ---- S = Q @ K^T ----
        float accs[8][4];
#pragma unroll
        for (int j = 0; j < 8; j++)
#pragma unroll
            for (int r = 0; r < 4; r++) accs[j][r] = 0.0f;

#pragma unroll
        for (int jp = 0; jp < 4; ++jp) {
#pragma unroll
            for (int ks = 0; ks < 8; ++ks) {
                uint32_t bb[4];
                ldsm4(bb, sKc + kb4_off + (uint32_t)(jp * 16 * FP + ks * 16) * 2u);
                mma_f16(accs[jp * 2], qf[ks], bb);
                mma_f16(accs[jp * 2 + 1], qf[ks], bb + 2);
            }
        }

        if (kt == qt) {
#pragma unroll
            for (int j = 0; j < 8; ++j) {
                const int c0 = j * 8 + 2 * q4;
                if (c0 > ar)          accs[j][0] = -1e30f;
                if (c0 + 1 > ar)      accs[j][1] = -1e30f;
                if (c0 > ar + 8)      accs[j][2] = -1e30f;
                if (c0 + 1 > ar + 8)  accs[j][3] = -1e30f;
            }
        }

        // ---- online softmax (exp2 domain, f16x2 MUFU) ----
        float mx0 = -INFINITY, mx1 = -INFINITY;
#pragma unroll
        for (int j = 0; j < 8; ++j) {
            mx0 = fmaxf(mx0, fmaxf(accs[j][0], accs[j][1]));
            mx1 = fmaxf(mx1, fmaxf(accs[j][2], accs[j][3]));
        }
        mx0 = fmaxf(mx0, __shfl_xor_sync(0xffffffffu, mx0, 1));
        mx0 = fmaxf(mx0, __shfl_xor_sync(0xffffffffu, mx0, 2));
        mx1 = fmaxf(mx1, __shfl_xor_sync(0xffffffffu, mx1, 1));
        mx1 = fmaxf(mx1, __shfl_xor_sync(0xffffffffu, mx1, 2));
        const float mn0 = fmaxf(m0, mx0);
        const float mn1 = fmaxf(m1, mx1);
        const float cr0 = exp2f(m0 - mn0);
        const float cr1 = exp2f(m1 - mn1);

        uint32_t p01[8], p23[8];
        float s0 = 0.0f, s1 = 0.0f;
#pragma unroll
        for (int j = 0; j < 8; ++j) {
            p01[j] = ex2_h2(accs[j][0] - mn0, accs[j][1] - mn0);
            p23[j] = ex2_h2(accs[j][2] - mn1, accs[j][3] - mn1);
            float2 f0 = __half22float2(*(__half2*)&p01[j]);
            float2 f1 = __half22float2(*(__half2*)&p23[j]);
            s0 += f0.x + f0.y;
            s1 += f1.x + f1.y;
        }
        s0 += __shfl_xor_sync(0xffffffffu, s0, 1);
        s0 += __shfl_xor_sync(0xffffffffu, s0, 2);
        s1 += __shfl_xor_sync(0xffffffffu, s1, 1);
        s1 += __shfl_xor_sync(0xffffffffu, s1, 2);
        l0 = l0 * cr0 + s0;  m0 = mn0;
        l1 = l1 * cr1 + s1;  m1 = mn1;
#pragma unroll
        for (int j = 0; j < 16; ++j) {
            acco[j][0] *= cr0; acco[j][1] *= cr0;
            acco[j][2] *= cr1; acco[j][3] *= cr1;
        }

        // ---- O += P @ V ----
#pragma unroll
        for (int t = 0; t < 4; ++t) {
            uint32_t a[4];
            a[0] = p01[2 * t];
            a[1] = p23[2 * t];
            a[2] = p01[2 * t + 1];
            a[3] = p23[2 * t + 1];
#pragma unroll
            for (int jp = 0; jp < 8; ++jp) {
                uint32_t bb[4];
                ldsm4t(bb, sVc + vt4_off + (uint32_t)(t * 16 * FP + jp * 16) * 2u);
                mma_f16(acco[jp * 2], a, bb);
                mma_f16(acco[jp * 2 + 1], a, bb + 2);
            }
        }
    }

    const float i0 = 1.0f / l0;
    const float i1 = 1.0f / l1;
#pragma unroll
    for (int j = 0; j < 16; ++j) {
        *(__half2*)(O + headoff + (size_t)(q0 + ar) * DMODEL + j * 8 + 2 * q4) =
            __floats2half2_rn(acco[j][0] * i0, acco[j][1] * i0);
        *(__half2*)(O + headoff + (size_t)(q0 + ar + 8) * DMODEL + j * 8 + 2 * q4) =
            __floats2half2_rn(acco[j][2] * i1, acco[j][3] * i1);
    }
}

// ---------------------------------------------------------------------------
extern "C" void kernel_launch(void* const* d_in, const int* in_sizes, int n_in,
                              void* d_out, int out_size)
{
    const float* query = (const float*)d_in[0];
    const float* key_i = (const float*)d_in[1];
    const float* value = (const float*)d_in[2];
    const float* Wq = (const float*)d_in[3];
    const float* bq = (const float*)d_in[4];
    const float* Wk = (const float*)d_in[5];
    const float* bk = (const float*)d_in[6];
    const float* Wv = (const float*)d_in[7];
    const float* bv = (const float*)d_in[8];
    const float* Wo = (const float*)d_in[9];
    const float* bo = (const float*)d_in[10];
    float* out = (float*)d_out;

    __half *xq, *xk, *xv, *wq, *wk, *wv, *wo, *pq, *pk, *pv, *pa;
    cudaGetSymbolAddress((void**)&xq, hx_q);
    cudaGetSymbolAddress((void**)&xk, hx_k);
    cudaGetSymbolAddress((void**)&xv, hx_v);
    cudaGetSymbolAddress((void**)&wq, hw_q);
    cudaGetSymbolAddress((void**)&wk, hw_k);
    cudaGetSymbolAddress((void**)&wv, hw_v);
    cudaGetSymbolAddress((void**)&wo, hw_o);
    cudaGetSymbolAddress((void**)&pq, h_q);
    cudaGetSymbolAddress((void**)&pk, h_k);
    cudaGetSymbolAddress((void**)&pv, h_v);
    cudaGetSymbolAddress((void**)&pa, h_a);

    conv_all<<<dim3(ACT_BLOCKS, 7), 256>>>(
        (const float4*)query, (const float4*)key_i, (const float4*)value,
        (const float4*)Wq, (const float4*)Wk, (const float4*)Wv,
        (const float4*)Wo,
        (uint2*)xq, (uint2*)xk, (uint2*)xv,
        (uint2*)wq, (uint2*)wk, (uint2*)wv, (uint2*)wo);

    cudaFuncSetAttribute(gemm_qkv, cudaFuncAttributeMaxDynamicSharedMemorySize,
                         GEMM_SMEM);
    cudaFuncSetAttribute(gemm_one, cudaFuncAttributeMaxDynamicSharedMemorySize,
                         GEMM_SMEM);

    gemm_qkv<<<dim3(GN / TBN, MROWS / TBM, 3), GEMM_THREADS, GEMM_SMEM>>>(
        xq, xk, xv, wq, wk, wv, bq, bk, bv, pq, pk, pv);

    cudaFuncSetAttribute(flash_tc, cudaFuncAttributeMaxDynamicSharedMemorySize,
                         FLASH_SMEM);
    const dim3 agrid(NQT, NHEAD, BATCH);   // 1024 CTAs
    flash_tc<<<agrid, FLASH_THREADS, FLASH_SMEM>>>(pq, pk, pv, pa);

    gemm_one<<<dim3(GN / TBN, MROWS / TBM), GEMM_THREADS, GEMM_SMEM>>>(
        pa, wo, bo, out, 1.0f, 0);
}

// round 15
// speedup vs baseline: 1.0060x; 1.0060x over previous
#include <cuda_runtime.h>
#include <cuda_fp16.h>
#include <math.h>
#include <stdint.h>

#define BATCH 2
#define SEQ 2048
#define DMODEL 2048
#define NHEAD 16
#define HDIM 128
#define MROWS (BATCH * SEQ)          // 4096
#define ATT_SCALE 0.08838834764831845f  // 1/sqrt(128)
#define LOG2E 1.4426950408889634f

// Scratch (device globals: allocation-free per harness rules)
__device__ __half hx_q[(size_t)MROWS * DMODEL];   // fp16 inputs
__device__ __half hx_k[(size_t)MROWS * DMODEL];
__device__ __half hx_v[(size_t)MROWS * DMODEL];
__device__ __half hw_q[(size_t)DMODEL * DMODEL];  // fp16 weights
__device__ __half hw_k[(size_t)DMODEL * DMODEL];
__device__ __half hw_v[(size_t)DMODEL * DMODEL];
__device__ __half hw_o[(size_t)DMODEL * DMODEL];
__device__ __half h_q[(size_t)MROWS * DMODEL];    // projected q (pre-scaled)
__device__ __half h_k[(size_t)MROWS * DMODEL];
__device__ __half h_v[(size_t)MROWS * DMODEL];
__device__ __half h_a[(size_t)MROWS * DMODEL];    // attention output

// ===========================================================================
// helpers
// ===========================================================================
__device__ __forceinline__ uint32_t smem_u32(const void* p) {
    uint32_t a;
    asm("{ .reg .u64 t; cvta.to.shared.u64 t, %1; cvt.u32.u64 %0, t; }"
        : "=r"(a) : "l"(p));
    return a;
}

__device__ __forceinline__ void cp16(uint32_t dst, const void* src) {
    asm volatile("cp.async.cg.shared.global [%0], [%1], 16;"
                 :: "r"(dst), "l"(src));
}

__device__ __forceinline__ void mma_f16(float* d, const uint32_t* a,
                                        const uint32_t* b)
{
    asm volatile(
        "mma.sync.aligned.m16n8k16.row.col.f32.f16.f16.f32 "
        "{%0,%1,%2,%3}, {%4,%5,%6,%7}, {%8,%9}, {%0,%1,%2,%3};"
        : "+f"(d[0]), "+f"(d[1]), "+f"(d[2]), "+f"(d[3])
        : "r"(a[0]), "r"(a[1]), "r"(a[2]), "r"(a[3]),
          "r"(b[0]), "r"(b[1]));
}

__device__ __forceinline__ void ldsm4(uint32_t* r, uint32_t a) {
    asm volatile("ldmatrix.sync.aligned.m8n8.x4.shared.b16 {%0,%1,%2,%3}, [%4];"
                 : "=r"(r[0]), "=r"(r[1]), "=r"(r[2]), "=r"(r[3]) : "r"(a));
}
__device__ __forceinline__ void ldsm4t(uint32_t* r, uint32_t a) {
    asm volatile("ldmatrix.sync.aligned.m8n8.x4.trans.shared.b16 {%0,%1,%2,%3}, [%4];"
                 : "=r"(r[0]), "=r"(r[1]), "=r"(r[2]), "=r"(r[3]) : "r"(a));
}

// exp2 on a packed pair of (fp32 -> fp16) values; result is an MMA A-frag word
__device__ __forceinline__ uint32_t ex2_h2(float x, float y) {
    __half2 hv = __floats2half2_rn(x, y);
    uint32_t u = *(uint32_t*)&hv;
    uint32_t r;
    asm("ex2.approx.f16x2 %0, %1;" : "=r"(r) : "r"(u));
    return r;
}

// ===========================================================================
// single fp32 -> fp16 conversion pass: z = 0..2 activations, 3..6 weights
// ===========================================================================
__device__ __forceinline__ uint2 cvt4(float4 v) {
    union { __half2 h[2]; uint2 u; } p;
    p.h[0] = __floats2half2_rn(v.x, v.y);
    p.h[1] = __floats2half2_rn(v.z, v.w);
    return p.u;
}

#define ACT_BLOCKS ((MROWS * DMODEL / 4) / 1024)   // 2048
#define W_BLOCKS ((DMODEL * DMODEL / 4) / 1024)    // 1024

__global__ void conv_all(const float4* __restrict__ q,
                         const float4* __restrict__ k,
                         const float4* __restrict__ v,
                         const float4* __restrict__ w0,
                         const float4* __restrict__ w1,
                         const float4* __restrict__ w2,
                         const float4* __restrict__ w3,
                         uint2* __restrict__ oq, uint2* __restrict__ ok,
                         uint2* __restrict__ ov,
                         uint2* __restrict__ o0, uint2* __restrict__ o1,
                         uint2* __restrict__ o2, uint2* __restrict__ o3)
{
    const int z = blockIdx.y;
    const float4* src;
    uint2* dst;
    if (z < 3) {
        src = (z == 0) ? q : (z == 1) ? k : v;
        dst = (z == 0) ? oq : (z == 1) ? ok : ov;
    } else {
        if (blockIdx.x >= W_BLOCKS) return;
        src = (z == 3) ? w0 : (z == 4) ? w1 : (z == 5) ? w2 : w3;
        dst = (z == 3) ? o0 : (z == 4) ? o1 : (z == 5) ? o2 : o3;
    }
    const int base = blockIdx.x * 1024 + threadIdx.x;
    float4 v0 = src[base];
    float4 v1 = src[base + 256];
    float4 v2 = src[base + 512];
    float4 v3 = src[base + 768];
    dst[base] = cvt4(v0);
    dst[base + 256] = cvt4(v1);
    dst[base + 512] = cvt4(v2);
    dst[base + 768] = cvt4(v3);
}

// ===========================================================================
// fp16 mma.sync GEMM core v4: CTA 128x128, 128 threads, 4 warps (2x2 of
// 64x64), BK=64, 2-stage cp.async, single sync/K-iter, PERSISTENT tiles.
// ===========================================================================
#define TBM 128
#define TBN 128
#define GK 2048
#define GN 2048
#define GBKH 64
#define AP 72
#define ASTGH (TBM * AP)
#define BSTGH (TBN * AP)
#define STGH (ASTGH + BSTGH)
#define GEMM_SMEM (2 * STGH * 2)      // 73728 B -> 3 CTAs/SM
#define NT (GK / GBKH)                // 32
#define GEMM_THREADS 128
#define NSM 148
#define GEMM_GRID (NSM * 3)           // 444 persistent CTAs
#define TILES_PER_GEMM ((GN / TBN) * (MROWS / TBM))   // 16 * 32 = 512

__device__ __forceinline__ void gemm_core(
    const __half* __restrict__ A, const __half* __restrict__ W,
    const float* __restrict__ bias, void* __restrict__ Cout,
    float scale, int half_out, int bx, int by)
{
    extern __shared__ __half gsmh[];

    const int tid = threadIdx.x;
    const int lane = tid & 31;
    const int warp = tid >> 5;
    const int wm = warp & 1;
    const int wn = warp >> 1;
    const int m0 = by * TBM;
    const int n0 = bx * TBN;

    const uint32_t sbase = smem_u32(gsmh);
    const int cr = tid >> 3;
    const int cc = tid & 7;

    float acc[4][8][4];
#pragma unroll
    for (int i = 0; i < 4; i++)
#pragma unroll
        for (int j = 0; j < 8; j++)
#pragma unroll
            for (int r = 0; r < 4; r++) acc[i][j][r] = 0.0f;

    auto issue = [&](int t, int buf) {
        const __half* Ab = A + (size_t)m0 * GK + t * GBKH;
        const __half* Wb = W + (size_t)n0 * GK + t * GBKH;
        const uint32_t sa = sbase + (uint32_t)buf * STGH * 2u;
        const uint32_t sb = sa + ASTGH * 2u;
#pragma unroll
        for (int i = 0; i < 8; i++) {
            const int r = cr + i * 16;
            cp16(sa + (uint32_t)(r * AP + cc * 8) * 2u,
                 Ab + (size_t)r * GK + cc * 8);
            cp16(sb + (uint32_t)(r * AP + cc * 8) * 2u,
                 Wb + (size_t)r * GK + cc * 8);
        }
        asm volatile("cp.async.commit_group;");
    };

    issue(0, 0);

    const uint32_t a_lane_off =
        (uint32_t)((wm * 64 + (lane & 15)) * AP + ((lane >> 4) * 8)) * 2u;
    const uint32_t b_lane_off =
        (uint32_t)((wn * 64 + (lane & 7) + ((lane >> 4) & 1) * 8) * AP
                   + (((lane >> 3) & 1) * 8)) * 2u;

    for (int t = 0; t < NT; ++t) {
        asm volatile("cp.async.wait_group 0;");
        __syncthreads();
        if (t + 1 < NT) issue(t + 1, (t + 1) & 1);

        const uint32_t sa = sbase + (uint32_t)(t & 1) * STGH * 2u;
        const uint32_t aaddr = sa + a_lane_off;
        const uint32_t baddr = sa + ASTGH * 2u + b_lane_off;

#pragma unroll
        for (int ks = 0; ks < 4; ++ks) {
            uint32_t bf[4][4];
#pragma unroll
            for (int np = 0; np < 4; np++)
                ldsm4(bf[np], baddr + (uint32_t)(np * 16 * AP + ks * 16) * 2u);
#pragma unroll
            for (int ms = 0; ms < 4; ms++) {
                uint32_t af[4];
                ldsm4(af, aaddr + (uint32_t)(ms * 16 * AP + ks * 16) * 2u);
#pragma unroll
                for (int np = 0; np < 4; np++) {
                    mma_f16(acc[ms][np * 2], af, bf[np]);
                    mma_f16(acc[ms][np * 2 + 1], af, bf[np] + 2);
                }
            }
        }
        __syncthreads();   // reads of this buffer done (safe for next issue /
                           // next tile's issue(0,0))
    }

    float2 bv[8];
#pragma unroll
    for (int ns = 0; ns < 8; ns++) {
        const int col = n0 + wn * 64 + ns * 8 + 2 * (lane & 3);
        bv[ns] = *(const float2*)(bias + col);
    }

    if (half_out) {
        __half* C = (__half*)Cout;
#pragma unroll
        for (int ms = 0; ms < 4; ms++) {
            const int row0 = m0 + wm * 64 + ms * 16 + (lane >> 2);
#pragma unroll
            for (int ns = 0; ns < 8; ns++) {
                const int col = n0 + wn * 64 + ns * 8 + 2 * (lane & 3);
                __half2 v0 = __floats2half2_rn((acc[ms][ns][0] + bv[ns].x) * scale,
                                               (acc[ms][ns][1] + bv[ns].y) * scale);
                __half2 v1 = __floats2half2_rn((acc[ms][ns][2] + bv[ns].x) * scale,
                                               (acc[ms][ns][3] + bv[ns].y) * scale);
                *(__half2*)(C + (size_t)row0 * GN + col) = v0;
                *(__half2*)(C + (size_t)(row0 + 8) * GN + col) = v1;
            }
        }
    } else {
        float* C = (float*)Cout;
#pragma unroll
        for (int ms = 0; ms < 4; ms++) {
            const int row0 = m0 + wm * 64 + ms * 16 + (lane >> 2);
#pragma unroll
            for (int ns = 0; ns < 8; ns++) {
                const int col = n0 + wn * 64 + ns * 8 + 2 * (lane & 3);
                float2 v0 = make_float2(acc[ms][ns][0] + bv[ns].x,
                                        acc[ms][ns][1] + bv[ns].y);
                float2 v1 = make_float2(acc[ms][ns][2] + bv[ns].x,
                                        acc[ms][ns][3] + bv[ns].y);
                *(float2*)(C + (size_t)row0 * GN + col) = v0;
                *(float2*)(C + (size_t)(row0 + 8) * GN + col) = v1;
            }
        }
    }
}

// persistent fused Q/K/V projection: 1536 tiles over 444 CTAs
__global__ __launch_bounds__(GEMM_THREADS, 3)
void gemm_qkv(const __half* __restrict__ xq, const __half* __restrict__ xk,
              const __half* __restrict__ xv,
              const __half* __restrict__ wq, const __half* __restrict__ wk,
              const __half* __restrict__ wv,
              const float* __restrict__ bq, const float* __restrict__ bk,
              const float* __restrict__ bv,
              __half* __restrict__ pq, __half* __restrict__ pk,
              __half* __restrict__ pv)
{
    for (int tile = blockIdx.x; tile < 3 * TILES_PER_GEMM; tile += gridDim.x) {
        const int z = tile >> 9;              // tile / 512
        const int rem = tile & 511;
        const int by = rem >> 4;              // 0..31
        const int bx = rem & 15;              // 0..15
        const __half* A = (z == 0) ? xq : (z == 1) ? xk : xv;
        const __half* W = (z == 0) ? wq : (z == 1) ? wk : wv;
        const float* bias = (z == 0) ? bq : (z == 1) ? bk : bv;
        __half* C = (z == 0) ? pq : (z == 1) ? pk : pv;
        const float scale = (z == 0) ? (ATT_SCALE * LOG2E) : 1.0f;
        gemm_core(A, W, bias, C, scale, 1, bx, by);
        __syncthreads();   // epilogue reads of regs done; smem reuse safe
    }
}

// persistent single GEMM: 512 tiles over 444 CTAs
__global__ __launch_bounds__(GEMM_THREADS, 3)
void gemm_one(const __half* __restrict__ A, const __half* __restrict__ W,
              const float* __restrict__ bias, void* __restrict__ Cout,
              float scale, int half_out)
{
    for (int tile = blockIdx.x; tile < TILES_PER_GEMM; tile += gridDim.x) {
        const int by = tile >> 4;
        const int bx = tile & 15;
        gemm_core(A, W, bias, Cout, scale, half_out, bx, by);
        __syncthreads();
    }
}

// ===========================================================================
// fp16 flash attention v6 (unchanged from R14): 64-q-row CTAs, 2 CTAs/SM,
// ex2.approx.f16x2 softmax, single sync per tile.
// ===========================================================================
#define FQ 64
#define FK 64
#define FP 136
#define QTILE_H (FQ * FP)
#define KTILE_H (FK * FP)
#define FLASH_SMEM ((QTILE_H + 4 * KTILE_H) * 2)   // 87040 B
#define FLASH_THREADS 128
#define NQT (SEQ / FQ)                 // 32

__global__ __launch_bounds__(FLASH_THREADS, 2)
void flash_tc(const __half* __restrict__ Q, const __half* __restrict__ K,
              const __half* __restrict__ V, __half* __restrict__ O)
{
    extern __shared__ __half fsmh[];

    const int qt = NQT - 1 - blockIdx.x;   // heavy tiles first
    const int h = blockIdx.y;
    const int b = blockIdx.z;
    const int q0 = qt * FQ;
    const size_t headoff = (size_t)b * SEQ * DMODEL + (size_t)h * HDIM;
    const __half* Qb = Q + headoff;
    const __half* Kb = K + headoff;
    const __half* Vb = V + headoff;

    const int tid = threadIdx.x;
    const int lane = tid & 31;
    const int warp = tid >> 5;
    const int g = lane >> 2;
    const int q4 = lane & 3;

    const uint32_t sQ = smem_u32(fsmh);
    const uint32_t sK0 = sQ + QTILE_H * 2u;
    const uint32_t sV0 = sQ + (QTILE_H + 2 * KTILE_H) * 2u;

#pragma unroll
    for (int i = 0; i < 8; ++i) {
        const int slot = tid + i * FLASH_THREADS;
        const int r = slot >> 4, c = slot & 15;
        cp16(sQ + (uint32_t)(r * FP + c * 8) * 2u,
             Qb + (size_t)(q0 + r) * DMODEL + c * 8);
    }

    auto issue_kv = [&](int kt) {
        const int buf = kt & 1;
        const int k0 = kt * FK;
        const uint32_t dK = sK0 + (uint32_t)buf * KTILE_H * 2u;
        const uint32_t dV = sV0 + (uint32_t)buf * KTILE_H * 2u;
#pragma unroll
        for (int i = 0; i < 8; ++i) {
            const int slot = tid + i * FLASH_THREADS;
            const int r = slot >> 4, c = slot & 15;
            cp16(dK + (uint32_t)(r * FP + c * 8) * 2u,
                 Kb + (size_t)(k0 + r) * DMODEL + c * 8);
            cp16(dV + (uint32_t)(r * FP + c * 8) * 2u,
                 Vb + (size_t)(k0 + r) * DMODEL + c * 8);
        }
        asm volatile("cp.async.commit_group;");
    };

    issue_kv(0);   // group 0 = Q + KV0

    float m0 = -INFINITY, m1 = -INFINITY, l0 = 0.0f, l1 = 0.0f;
    float acco[16][4];
#pragma unroll
    for (int j = 0; j < 16; j++)
#pragma unroll
        for (int r = 0; r < 4; r++) acco[j][r] = 0.0f;

    const int ar = warp * 16 + g;

    const uint32_t qa_off =
        (uint32_t)((warp * 16 + (lane & 15)) * FP + ((lane >> 4) * 8)) * 2u;
    const uint32_t kb4_off =
        (uint32_t)(((lane & 7) + ((lane >> 4) & 1) * 8) * FP
                   + (((lane >> 3) & 1) * 8)) * 2u;
    const uint32_t vt4_off =
        (uint32_t)(((lane & 7) + ((lane >> 3) & 1) * 8) * FP
                   + ((lane >> 4) * 8)) * 2u;

    uint32_t qf[8][4];
    bool qloaded = false;

    for (int kt = 0; kt <= qt; ++kt) {
        const int buf = kt & 1;
        const uint32_t sKc = sK0 + (uint32_t)buf * KTILE_H * 2u;
        const uint32_t sVc = sV0 + (uint32_t)buf * KTILE_H * 2u;

        asm volatile("cp.async.wait_group 0;");
        __syncthreads();
        if (kt + 1 <= qt) issue_kv(kt + 1);

        if (!qloaded) {
#pragma unroll
            for (int ks = 0; ks < 8; ++ks)
                ldsm4(qf[ks], sQ + qa_off + (uint32_t)(ks * 16) * 2u);
            qloaded = true;
        }

        // ---- S = Q @ K^T ----
        float accs[8][4];
#pragma unroll
        for (int j = 0; j < 8; j++)
#pragma unroll
            for (int r = 0; r < 4; r++) accs[j][r] = 0.0f;

#pragma unroll
        for (int jp = 0; jp < 4; ++jp) {
#pragma unroll
            for (int ks = 0; ks < 8; ++ks) {
                uint32_t bb[4];
                ldsm4(bb, sKc + kb4_off + (uint32_t)(jp * 16 * FP + ks * 16) * 2u);
                mma_f16(accs[jp * 2], qf[ks], bb);
                mma_f16(accs[jp * 2 + 1], qf[ks], bb + 2);
            }
        }

        if (kt == qt) {
#pragma unroll
            for (int j = 0; j < 8; ++j) {
                const int c0 = j * 8 + 2 * q4;
                if (c0 > ar)          accs[j][0] = -1e30f;
                if (c0 + 1 > ar)      accs[j][1] = -1e30f;
                if (c0 > ar + 8)      accs[j][2] = -1e30f;
                if (c0 + 1 > ar + 8)  accs[j][3] = -1e30f;
            }
        }

        // ---- online softmax (exp2 domain, f16x2 MUFU) ----
        float mx0 = -INFINITY, mx1 = -INFINITY;
#pragma unroll
        for (int j = 0; j < 8; ++j) {
            mx0 = fmaxf(mx0, fmaxf(accs[j][0], accs[j][1]));
            mx1 = fmaxf(mx1, fmaxf(accs[j][2], accs[j][3]));
        }
        mx0 = fmaxf(mx0, __shfl_xor_sync(0xffffffffu, mx0, 1));
        mx0 = fmaxf(mx0, __shfl_xor_sync(0xffffffffu, mx0, 2));
        mx1 = fmaxf(mx1, __shfl_xor_sync(0xffffffffu, mx1, 1));
        mx1 = fmaxf(mx1, __shfl_xor_sync(0xffffffffu, mx1, 2));
        const float mn0 = fmaxf(m0, mx0);
        const float mn1 = fmaxf(m1, mx1);
        const float cr0 = exp2f(m0 - mn0);
        const float cr1 = exp2f(m1 - mn1);

        uint32_t p01[8], p23[8];
        float s0 = 0.0f, s1 = 0.0f;
#pragma unroll
        for (int j = 0; j < 8; ++j) {
            p01[j] = ex2_h2(accs[j][0] - mn0, accs[j][1] - mn0);
            p23[j] = ex2_h2(accs[j][2] - mn1, accs[j][3] - mn1);
            float2 f0 = __half22float2(*(__half2*)&p01[j]);
            float2 f1 = __half22float2(*(__half2*)&p23[j]);
            s0 += f0.x + f0.y;
            s1 += f1.x + f1.y;
        }
        s0 += __shfl_xor_sync(0xffffffffu, s0, 1);
        s0 += __shfl_xor_sync(0xffffffffu, s0, 2);
        s1 += __shfl_xor_sync(0xffffffffu, s1, 1);
        s1 += __shfl_xor_sync(0xffffffffu, s1, 2);
        l0 = l0 * cr0 + s0;  m0 = mn0;
        l1 = l1 * cr1 + s1;  m1 = mn1;
#pragma unroll
        for (int j = 0; j < 16; ++j) {
            acco[j][0] *= cr0; acco[j][1] *= cr0;
            acco[j][2] *= cr1; acco[j][3] *= cr1;
        }

        // ---- O += P @ V ----
#pragma unroll
        for (int t = 0; t < 4; ++t) {
            uint32_t a[4];
            a[0] = p01[2 * t];
            a[1] = p23[2 * t];
            a[2] = p01[2 * t + 1];
            a[3] = p23[2 * t + 1];
#pragma unroll
            for (int jp = 0; jp < 8; ++jp) {
                uint32_t bb[4];
                ldsm4t(bb, sVc + vt4_off + (uint32_t)(t * 16 * FP + jp * 16) * 2u);
                mma_f16(acco[jp * 2], a, bb);
                mma_f16(acco[jp * 2 + 1], a, bb + 2);
            }
        }
    }

    const float i0 = 1.0f / l0;
    const float i1 = 1.0f / l1;
#pragma unroll
    for (int j = 0; j < 16; ++j) {
        *(__half2*)(O + headoff + (size_t)(q0 + ar) * DMODEL + j * 8 + 2 * q4) =
            __floats2half2_rn(acco[j][0] * i0, acco[j][1] * i0);
        *(__half2*)(O + headoff + (size_t)(q0 + ar + 8) * DMODEL + j * 8 + 2 * q4) =
            __floats2half2_rn(acco[j][2] * i1, acco[j][3] * i1);
    }
}

// ---------------------------------------------------------------------------
extern "C" void kernel_launch(void* const* d_in, const int* in_sizes, int n_in,
                              void* d_out, int out_size)
{
    const float* query = (const float*)d_in[0];
    const float* key_i = (const float*)d_in[1];
    const float* value = (const float*)d_in[2];
    const float* Wq = (const float*)d_in[3];
    const float* bq = (const float*)d_in[4];
    const float* Wk = (const float*)d_in[5];
    const float* bk = (const float*)d_in[6];
    const float* Wv = (const float*)d_in[7];
    const float* bv = (const float*)d_in[8];
    const float* Wo = (const float*)d_in[9];
    const float* bo = (const float*)d_in[10];
    float* out = (float*)d_out;

    __half *xq, *xk, *xv, *wq, *wk, *wv, *wo, *pq, *pk, *pv, *pa;
    cudaGetSymbolAddress((void**)&xq, hx_q);
    cudaGetSymbolAddress((void**)&xk, hx_k);
    cudaGetSymbolAddress((void**)&xv, hx_v);
    cudaGetSymbolAddress((void**)&wq, hw_q);
    cudaGetSymbolAddress((void**)&wk, hw_k);
    cudaGetSymbolAddress((void**)&wv, hw_v);
    cudaGetSymbolAddress((void**)&wo, hw_o);
    cudaGetSymbolAddress((void**)&pq, h_q);
    cudaGetSymbolAddress((void**)&pk, h_k);
    cudaGetSymbolAddress((void**)&pv, h_v);
    cudaGetSymbolAddress((void**)&pa, h_a);

    conv_all<<<dim3(ACT_BLOCKS, 7), 256>>>(
        (const float4*)query, (const float4*)key_i, (const float4*)value,
        (const float4*)Wq, (const float4*)Wk, (const float4*)Wv,
        (const float4*)Wo,
        (uint2*)xq, (uint2*)xk, (uint2*)xv,
        (uint2*)wq, (uint2*)wk, (uint2*)wv, (uint2*)wo);

    cudaFuncSetAttribute(gemm_qkv, cudaFuncAttributeMaxDynamicSharedMemorySize,
                         GEMM_SMEM);
    cudaFuncSetAttribute(gemm_one, cudaFuncAttributeMaxDynamicSharedMemorySize,
                         GEMM_SMEM);

    gemm_qkv<<<GEMM_GRID, GEMM_THREADS, GEMM_SMEM>>>(
        xq, xk, xv, wq, wk, wv, bq, bk, bv, pq, pk, pv);

    cudaFuncSetAttribute(flash_tc, cudaFuncAttributeMaxDynamicSharedMemorySize,
                         FLASH_SMEM);
    const dim3 agrid(NQT, NHEAD, BATCH);   // 1024 CTAs
    flash_tc<<<agrid, FLASH_THREADS, FLASH_SMEM>>>(pq, pk, pv, pa);

    gemm_one<<<GEMM_GRID, GEMM_THREADS, GEMM_SMEM>>>(
        pa, wo, bo, out, 1.0f, 0);
}